// round 2
// baseline (speedup 1.0000x reference)
#include <cuda_runtime.h>
#include <cuda_bf16.h>

// Problem constants (fixed by the dataset)
#define BB 16
#define TT 32641
#define EE 128
#define LL (TT + EE - 1)           // 32768 groups (power of two)
#define RR 64                      // rows per tile
#define TILES ((TT + RR - 1) / RR) // 511
#define TPC 4                      // tiles per chunk (per block)
#define CHUNKS 128                 // 128*4 = 512 >= 511

// Scratch: per-(batch, group) partial sums. Zero at module load;
// finalize kernel re-zeroes them after reading, so every launch/replay
// starts from a clean state without a separate init kernel.
__device__ float g_S1[BB * LL];
__device__ float g_S2[BB * LL];
__device__ float g_acc;
__device__ unsigned int g_cnt;

// ---------------------------------------------------------------------------
// Diag kernel: software-pipelined anti-diagonal partial sums.
// Each block owns (batch b, tiles [k0, k0+TPC)). Per tile:
//   regs(prefetched) -> smem buf[k&1]; sync; issue LDGs for tile k+1;
//   walk diagonals from smem; atomics to global scratch.
// Single __syncthreads per tile; double buffering makes the 2-apart buffer
// reuse safe through the transitive sync ordering.
// ---------------------------------------------------------------------------
__global__ void __launch_bounds__(256) tcl_diag_kernel(const float* __restrict__ x) {
    extern __shared__ float buf[];   // 2 * RR*EE floats = 64 KB

    const int b   = blockIdx.y;
    const int tid = threadIdx.x;
    const float* xb = x + (size_t)b * TT * EE;

    const int k0 = blockIdx.x * TPC;
    const int k1 = min(k0 + TPC, TILES);
    const int nk = k1 - k0;
    if (nk <= 0) return;

    float4 reg[8];

    // Prefetch tile k0 into registers (rows >= TT zero-filled).
    {
        const int r0 = k0 * RR;
        #pragma unroll
        for (int u = 0; u < 8; ++u) {
            int v    = tid + u * 256;
            int row  = v >> 5;       // / (EE/4)
            int colv = v & 31;       // % (EE/4)
            int gr   = r0 + row;
            reg[u] = (gr < TT)
                   ? __ldg((const float4*)(xb + (size_t)gr * EE) + colv)
                   : make_float4(0.f, 0.f, 0.f, 0.f);
        }
    }

    for (int kk = 0; kk < nk; ++kk) {
        float* cur = buf + (kk & 1) * (RR * EE);

        // Stage prefetched registers into the current smem buffer.
        #pragma unroll
        for (int u = 0; u < 8; ++u) {
            ((float4*)cur)[tid + u * 256] = reg[u];
        }
        __syncthreads();

        // Issue next tile's global loads NOW so DRAM stays busy while we
        // compute from smem (scoreboard stall lands at next iter's STS).
        if (kk + 1 < nk) {
            const int r0n = (k0 + kk + 1) * RR;
            #pragma unroll
            for (int u = 0; u < 8; ++u) {
                int v    = tid + u * 256;
                int row  = v >> 5;
                int colv = v & 31;
                int gr   = r0n + row;
                reg[u] = (gr < TT)
                       ? __ldg((const float4*)(xb + (size_t)gr * EE) + colv)
                       : make_float4(0.f, 0.f, 0.f, 0.f);
            }
        }

        // Diagonal walk: thread d owns group t = r0 + d within this tile.
        // Reads cur[i*EE + (d-i)]: lanes d..d+31 at fixed i hit consecutive
        // addresses -> conflict-free.
        const int r0 = (k0 + kk) * RR;
        const int d  = tid;
        if (d < RR + EE - 1) {
            const int t    = r0 + d;
            const int tmax = min(r0 + RR, TT) - 1 + (EE - 1);
            if (t <= tmax) {
                const int i_lo = max(0, d - (EE - 1));
                const int i_hi = min(RR - 1, d);
                float s1 = 0.0f, s2 = 0.0f;
                #pragma unroll 4
                for (int i = i_lo; i <= i_hi; ++i) {
                    float v = cur[i * EE + (d - i)];
                    s1 += v;
                    s2 = fmaf(v, v, s2);
                }
                atomicAdd(&g_S1[b * LL + t], s1);
                atomicAdd(&g_S2[b * LL + t], s2);
            }
        }
        // No trailing sync needed: the next iteration's post-STS sync
        // transitively orders buffer reuse (2-apart with double buffer).
    }
}

// ---------------------------------------------------------------------------
// Finalize: var = S2/c - (S1/c)^2 with analytic counts, reduce to scalar.
// Also RESETS the scratch (read-then-zero) and the accumulator/counter so
// the next launch/replay starts clean. Last block writes out[0] directly
// (out is poisoned, so no atomicAdd on it).
// ---------------------------------------------------------------------------
__global__ void __launch_bounds__(256) tcl_finalize_kernel(float* __restrict__ out) {
    __shared__ float red[8];
    float local = 0.0f;
    const int stride = gridDim.x * blockDim.x;
    for (int g = blockIdx.x * blockDim.x + threadIdx.x; g < BB * LL; g += stride) {
        int t  = g & (LL - 1);                       // LL is a power of two
        int ci = min(min(t + 1, EE), LL - t);
        float inv_c = 1.0f / (float)ci;
        float s1 = g_S1[g];
        float s2 = g_S2[g];
        g_S1[g] = 0.0f;                               // reset for next replay
        g_S2[g] = 0.0f;
        float mean = s1 * inv_c;
        local += s2 * inv_c - mean * mean;
    }
    // intra-block reduce
    #pragma unroll
    for (int o = 16; o; o >>= 1) local += __shfl_down_sync(0xFFFFFFFFu, local, o);
    if ((threadIdx.x & 31) == 0) red[threadIdx.x >> 5] = local;
    __syncthreads();
    if (threadIdx.x < 8) {
        float v = red[threadIdx.x];
        #pragma unroll
        for (int o = 4; o; o >>= 1) v += __shfl_down_sync(0xFFu, v, o);
        if (threadIdx.x == 0) {
            atomicAdd(&g_acc, v);
            __threadfence();
            unsigned int ticket = atomicAdd(&g_cnt, 1u);
            if (ticket == gridDim.x - 1) {
                // all blocks' g_acc contributions are visible (fence+atomic order)
                out[0] = g_acc * (0.1f / ((float)BB * (float)LL));
                g_acc = 0.0f;                         // reset for next replay
                g_cnt = 0u;
                __threadfence();
            }
        }
    }
}

// ---------------------------------------------------------------------------
extern "C" void kernel_launch(void* const* d_in, const int* in_sizes, int n_in,
                              void* d_out, int out_size) {
    const float* x = (const float*)d_in[0];
    float* out = (float*)d_out;

    const int diag_smem = 2 * RR * EE * (int)sizeof(float);  // 64 KB
    cudaFuncSetAttribute(tcl_diag_kernel,
                         cudaFuncAttributeMaxDynamicSharedMemorySize, diag_smem);

    dim3 grid(CHUNKS, BB);
    tcl_diag_kernel<<<grid, 256, diag_smem>>>(x);

    tcl_finalize_kernel<<<512, 256>>>(out);
}